// round 12
// baseline (speedup 1.0000x reference)
#include <cuda_runtime.h>
#include <cuda_bf16.h>

// Depthwise 3x3 conv, stride 1, VALID, groups=C.
// x: (16, 64, 512, 512) fp32, w: (64, 3, 3) fp32 -> out: (16, 64, 510, 510) fp32.
//
// R10/R11: CHUNK 510 — one block per (n,c) image. Unconfounded tile-size
// test (R6 confounded CHUNK=128 with __stcs). 1024 blocks all resident in a
// single wave (cap 1184): zero wave transitions, zero redundant halo reads
// (each block reads its 512 rows exactly once). unroll 4 / plain stores =
// measured optimum from the R5-R9 sweep.
//
// Register-resident vertical sliding window: each thread owns 4 output
// columns, walks down the image with 3 rotating accumulators; every input
// row is loaded once (float4 + float2 halo) and feeds 3 output rows.

#define NIMG 1024      // N*C = 16*64
#define HH 512
#define WW 512
#define HO 510
#define WO 510

__global__ __launch_bounds__(128, 8)
void dwconv3x3_kernel(const float* __restrict__ x,
                      const float* __restrict__ wgt,
                      float* __restrict__ out)
{
    const int t  = threadIdx.x;        // 0..127, column group
    const int x4 = t * 4;              // first output column of this thread
    const int nc = blockIdx.x;         // 0..1023 (n*64 + c)
    const int c  = nc & 63;

    // Per-channel 3x3 weights into registers.
    const float* wp = wgt + c * 9;
    const float w00 = wp[0], w01 = wp[1], w02 = wp[2];
    const float w10 = wp[3], w11 = wp[4], w12 = wp[5];
    const float w20 = wp[6], w21 = wp[7], w22 = wp[8];

    const float* inimg  = x   + (size_t)nc * HH * WW;
    float*       outimg = out + (size_t)nc * HO * WO;

    // Rotating accumulators:
    //   a* : newest partial (weight-row-0 contribution only)
    //   b* : middle partial (weight rows 0 and 1)
    float a0 = 0.f, a1 = 0.f, a2 = 0.f, a3 = 0.f;
    float b0 = 0.f, b1 = 0.f, b2 = 0.f, b3 = 0.f;

    const bool full = (t < 127);  // t==127 handles output cols 508,509 only

    #pragma unroll 4
    for (int r = 0; r < HH; ++r) {
        const float* row = inimg + (size_t)r * WW + x4;
        const float4 va = *(const float4*)row;           // cols x4..x4+3 (16B aligned)
        float i4 = 0.f, i5 = 0.f;
        if (full) {
            const float2 vb = *(const float2*)(row + 4); // cols x4+4, x4+5
            i4 = vb.x; i5 = vb.y;
        }
        const float i0 = va.x, i1 = va.y, i2 = va.z, i3 = va.w;

        // Completed output row (yo = r - 2): add weight row 2.
        const float c0 = fmaf(w20, i0, fmaf(w21, i1, fmaf(w22, i2, b0)));
        const float c1 = fmaf(w20, i1, fmaf(w21, i2, fmaf(w22, i3, b1)));
        const float c2 = fmaf(w20, i2, fmaf(w21, i3, fmaf(w22, i4, b2)));
        const float c3 = fmaf(w20, i3, fmaf(w21, i4, fmaf(w22, i5, b3)));

        // Rotate: b_next = a + weight-row-1 * this row
        b0 = fmaf(w10, i0, fmaf(w11, i1, fmaf(w12, i2, a0)));
        b1 = fmaf(w10, i1, fmaf(w11, i2, fmaf(w12, i3, a1)));
        b2 = fmaf(w10, i2, fmaf(w11, i3, fmaf(w12, i4, a2)));
        b3 = fmaf(w10, i3, fmaf(w11, i4, fmaf(w12, i5, a3)));

        // a_next = weight-row-0 * this row
        a0 = fmaf(w00, i0, fmaf(w01, i1, w02 * i2));
        a1 = fmaf(w00, i1, fmaf(w01, i2, w02 * i3));
        a2 = fmaf(w00, i2, fmaf(w01, i3, w02 * i4));
        a3 = fmaf(w00, i3, fmaf(w01, i4, w02 * i5));

        const int yo = r - 2;
        if (yo >= 0) {
            // Output row stride is 510*4B (8B-aligned only) -> 2x STG.64.
            float* orow = outimg + (size_t)yo * WO + x4;
            *(float2*)orow = make_float2(c0, c1);
            if (full) *(float2*)(orow + 2) = make_float2(c2, c3);
        }
    }
}

extern "C" void kernel_launch(void* const* d_in, const int* in_sizes, int n_in,
                              void* d_out, int out_size)
{
    const float* x = (const float*)d_in[0];
    const float* w = (const float*)d_in[1];
    float* out = (float*)d_out;

    dwconv3x3_kernel<<<NIMG, 128>>>(x, w, out);
}

// round 13
// speedup vs baseline: 1.1287x; 1.1287x over previous
#include <cuda_runtime.h>
#include <cuda_bf16.h>

// Depthwise 3x3 conv, stride 1, VALID, groups=C.
// x: (16, 64, 512, 512) fp32, w: (64, 3, 3) fp32 -> out: (16, 64, 510, 510) fp32.
//
// FINAL (R12): measured-optimal configuration — CHUNK 64 (8192 blocks),
// unroll 4, plain STG.64 stores. Full sweep results:
//   unroll: 2 -> 333.3us, 4 -> 330.2us, 8 -> 339.4us
//   CHUNK:  64 -> 330.2us, 128 -> 336.5us, 510 -> 372.2us
//     (achieved DRAM% tracks resident-CTA oversubscription; 8192 blocks
//      at 8 CTAs/SM keeps the bus at 82.7% busy, grid=1024 starves it)
// DRAM traffic is compulsory-minimal (2.12 GB); remaining ~17% of HBM spec
// is mixed read/write-stream turnaround — at the practical roofline.
//
// Register-resident vertical sliding window: each thread owns 4 output
// columns, walks down a 64-row chunk with 3 rotating accumulators; every
// input row is loaded once (float4 + float2 halo) and feeds 3 output rows.

#define NIMG 1024      // N*C = 16*64
#define HH 512
#define WW 512
#define HO 510
#define WO 510
#define CHUNK 64       // output rows per block
#define NCHUNK 8       // ceil(510/64)

__global__ __launch_bounds__(128, 8)
void dwconv3x3_kernel(const float* __restrict__ x,
                      const float* __restrict__ wgt,
                      float* __restrict__ out)
{
    const int t  = threadIdx.x;        // 0..127, column group
    const int x4 = t * 4;              // first output column of this thread
    const int nc = blockIdx.y;         // 0..1023 (n*64 + c)
    const int y0 = blockIdx.x * CHUNK; // first output row of this chunk
    const int c  = nc & 63;

    // Per-channel 3x3 weights into registers.
    const float* wp = wgt + c * 9;
    const float w00 = wp[0], w01 = wp[1], w02 = wp[2];
    const float w10 = wp[3], w11 = wp[4], w12 = wp[5];
    const float w20 = wp[6], w21 = wp[7], w22 = wp[8];

    const float* inimg  = x   + (size_t)nc * HH * WW;
    float*       outimg = out + (size_t)nc * HO * WO;

    // Rotating accumulators:
    //   a* : newest partial (weight-row-0 contribution only)
    //   b* : middle partial (weight rows 0 and 1)
    float a0 = 0.f, a1 = 0.f, a2 = 0.f, a3 = 0.f;
    float b0 = 0.f, b1 = 0.f, b2 = 0.f, b3 = 0.f;

    const bool full = (t < 127);  // t==127 handles output cols 508,509 only
    const int rend = min(y0 + CHUNK + 2, HH);

    #pragma unroll 4
    for (int r = y0; r < rend; ++r) {
        const float* row = inimg + (size_t)r * WW + x4;
        const float4 va = *(const float4*)row;           // cols x4..x4+3 (16B aligned)
        float i4 = 0.f, i5 = 0.f;
        if (full) {
            const float2 vb = *(const float2*)(row + 4); // cols x4+4, x4+5
            i4 = vb.x; i5 = vb.y;
        }
        const float i0 = va.x, i1 = va.y, i2 = va.z, i3 = va.w;

        // Completed output row (yo = r - 2): add weight row 2.
        const float c0 = fmaf(w20, i0, fmaf(w21, i1, fmaf(w22, i2, b0)));
        const float c1 = fmaf(w20, i1, fmaf(w21, i2, fmaf(w22, i3, b1)));
        const float c2 = fmaf(w20, i2, fmaf(w21, i3, fmaf(w22, i4, b2)));
        const float c3 = fmaf(w20, i3, fmaf(w21, i4, fmaf(w22, i5, b3)));

        // Rotate: b_next = a + weight-row-1 * this row
        b0 = fmaf(w10, i0, fmaf(w11, i1, fmaf(w12, i2, a0)));
        b1 = fmaf(w10, i1, fmaf(w11, i2, fmaf(w12, i3, a1)));
        b2 = fmaf(w10, i2, fmaf(w11, i3, fmaf(w12, i4, a2)));
        b3 = fmaf(w10, i3, fmaf(w11, i4, fmaf(w12, i5, a3)));

        // a_next = weight-row-0 * this row
        a0 = fmaf(w00, i0, fmaf(w01, i1, w02 * i2));
        a1 = fmaf(w00, i1, fmaf(w01, i2, w02 * i3));
        a2 = fmaf(w00, i2, fmaf(w01, i3, w02 * i4));
        a3 = fmaf(w00, i3, fmaf(w01, i4, w02 * i5));

        const int yo = r - 2;
        if (yo >= y0) {
            // Output row stride is 510*4B (8B-aligned only) -> 2x STG.64.
            float* orow = outimg + (size_t)yo * WO + x4;
            *(float2*)orow = make_float2(c0, c1);
            if (full) *(float2*)(orow + 2) = make_float2(c2, c3);
        }
    }
}

extern "C" void kernel_launch(void* const* d_in, const int* in_sizes, int n_in,
                              void* d_out, int out_size)
{
    const float* x = (const float*)d_in[0];
    const float* w = (const float*)d_in[1];
    float* out = (float*)d_out;

    dim3 grid(NCHUNK, NIMG);
    dwconv3x3_kernel<<<grid, 128>>>(x, w, out);
}